// round 15
// baseline (speedup 1.0000x reference)
#include <cuda_runtime.h>
#include <cuda_fp16.h>
#include <math.h>

#define LL   32768
#define CHN  128
#define NCHK 256
#define CHP  131
#define PAD  132

// ---------------- static device scratch ----------------
__device__ float  gXf [2*48*LL];
__device__ float  gYf [2*48*LL];
__device__ __half gY0h[4*48*LL];
__device__ float  gSdt[4*48*LL];
__device__ __half gZsh[4*48*LL];
__device__ __half gCmh[4*8*LL];
__device__ float  gHend[4*NCHK*384];
__device__ float  gSsum[4*NCHK*48];
__device__ float  gH0c [4*NCHK*384];

__device__ __forceinline__ float silu_f(float v) { return __fdividef(v, 1.f + __expf(-v)); }

// ---------------- fused rotation ----------------
__global__ void k_rot()
{
    __shared__ float tile[4][32][33];
    int bc = blockIdx.y, f0 = blockIdx.x * 4;
    int tx = threadIdx.x, ty = threadIdx.y;
    const float* s = gYf + (size_t)bc * LL;
    float* d = gXf + (size_t)bc * LL;
    #pragma unroll
    for (int k = 0; k < 4; k++)
        tile[k][ty][tx] = s[ty*1024 + (f0+k)*32 + tx];
    __syncthreads();
    #pragma unroll
    for (int k = 0; k < 4; k++)
        d[(f0+k)*1024 + ty*32 + tx] = tile[k][tx][ty];
}

// ---------------- final ----------------
__global__ void k_final(float* extd, const float* __restrict__ xext)
{
    __shared__ float tile[4][32][33];
    int bc = blockIdx.y, f0 = blockIdx.x * 4;
    int tx = threadIdx.x, ty = threadIdx.y;
    const float* s = gYf + (size_t)bc * LL;
    const float* xb = xext + (size_t)bc * LL;
    float* d = extd + (size_t)bc * LL;
    #pragma unroll
    for (int k = 0; k < 4; k++)
        tile[k][ty][tx] = s[ty*1024 + (f0+k)*32 + tx];
    __syncthreads();
    #pragma unroll
    for (int k = 0; k < 4; k++) {
        int o = (f0+k)*1024 + ty*32 + tx;
        d[o] = tile[k][tx][ty] + xb[o];
    }
}

// ---------------- K1: features (LN folded) + stateless two-pass scan, occ 3 ----------------
__global__ __launch_bounds__(384, 3) void k_features(
    const float* __restrict__ ln_g, const float* __restrict__ ln_b,
    const float* __restrict__ in_w, const float* __restrict__ conv_w,
    const float* __restrict__ conv_b, const float* __restrict__ xproj_w,
    const float* __restrict__ dt_w, const float* __restrict__ dt_b,
    const float* __restrict__ A_log, const float* __restrict__ Dpar,
    const float* __restrict__ xext, int useX, int iter)
{
    int ck = blockIdx.x, e = blockIdx.y, b = blockIdx.z;
    int p = 2*iter + e, be = b*2 + e, l0 = ck*CHN, tid = threadIdx.x;

    extern __shared__ float sm[];
    float* s_x    = sm;                 // [48][PAD] RAW x (dead after in_proj)
    float* s_dtin = s_x;                // ALIAS [2][PAD]
    float* s_bt   = s_x + 264;          // ALIAS [2592]
    float* s_xc   = sm + 48*PAD;        // [48][PAD]
    float* s_wi   = s_xc + 48*PAD;      // [24][96]
    float* s_cw   = s_wi + 2304;        // [48][4]
    float* s_cb   = s_cw + 192;
    float* s_xw   = s_cb + 48;          // [48][20]
    float* s_dtw  = s_xw + 960;
    float* s_dtb  = s_dtw + 96;
    float* s_g    = s_dtb + 48;
    float* s_bb   = s_g + 48;
    float* s_Dp   = s_bb + 48;
    float* s_mu   = s_Dp + 48;          // [132]
    float* s_rs   = s_mu + 132;         // [132]
    float* s_S1   = s_rs + 132;         // [96]
    float* s_S2   = s_S1 + 96;          // [96]
    float* s_paS  = s_S2 + 96;          // [3*128]
    float* s_paQ  = s_paS + 384;        // [3*128]

    // ---- loads ----
    for (int i = tid; i < 2304; i += 384) {
        int eo = i/24, dd = i%24;
        s_wi[dd*96 + eo] = in_w[p*2304 + i];
    }
    for (int i = tid; i < 192; i += 384) s_cw[i] = conv_w[p*192 + i];
    for (int i = tid; i < 864; i += 384) {
        int e2 = i/48, d = i%48;
        s_xw[d*20 + e2] = xproj_w[p*864 + i];
    }
    for (int i = tid; i < 96; i += 384) s_xw[(i>>1)*20 + 18 + (i&1)] = 0.f;
    for (int i = tid; i < 96; i += 384) s_dtw[i] = dt_w[p*96 + i];
    if (tid < 48) {
        s_cb[tid]  = conv_b[p*48 + tid];  s_dtb[tid] = dt_b[p*48 + tid];
        s_g[tid]   = ln_g[iter*48 + tid]; s_bb[tid]  = ln_b[iter*48 + tid];
        s_Dp[tid]  = Dpar[p*48 + tid];
    }
    const float* xfb = (useX ? xext : (const float*)gXf) + (size_t)b*48*LL;
    for (int i = tid; i < 48*PAD; i += 384) {
        int c = i/PAD, j = i%PAD;
        int l = l0 - 3 + j;
        float v = 0.f;
        if (j < CHP && l >= 0) {
            int t = (e == 0) ? l : (LL - 1 - l);
            v = xfb[(size_t)c*LL + t];
        }
        s_x[i] = v;
    }
    __syncthreads();

    // ---- phase A: LN partials + gamma-scale s_wi ----
    int c0 = e*24;
    {
        int pp = tid >> 7, j = tid & 127;
        int cA = pp*16;
        float su = 0.f, sq = 0.f;
        #pragma unroll
        for (int c = 0; c < 16; c++) {
            float xv = s_x[(cA + c)*PAD + j];
            su += xv; sq += xv*xv;
        }
        s_paS[pp*128 + j] = su;
        s_paQ[pp*128 + j] = sq;
    }
    for (int i = tid; i < 2304; i += 384) {
        int dd = i/96;
        s_wi[i] *= s_g[c0 + dd];
    }
    __syncthreads();

    // ---- phase B: combine LN partials + tail cols + S1/S2 ----
    if (tid < 128) {
        int j = tid;
        float su = s_paS[j] + s_paS[128 + j] + s_paS[256 + j];
        float sq = s_paQ[j] + s_paQ[128 + j] + s_paQ[256 + j];
        float mu = su*(1.f/48.f);
        float var = sq*(1.f/48.f) - mu*mu;
        s_mu[j] = mu;
        s_rs[j] = rsqrtf(var + 1e-5f);
    } else if (tid < 131) {
        int j = tid;
        float su = 0.f, sq = 0.f;
        #pragma unroll
        for (int c = 0; c < 48; c++) { float xv = s_x[c*PAD + j]; su += xv; sq += xv*xv; }
        float mu = su*(1.f/48.f);
        float var = sq*(1.f/48.f) - mu*mu;
        s_mu[j] = mu;
        s_rs[j] = rsqrtf(var + 1e-5f);
    } else if (tid >= 160 && tid < 256) {
        int eo = tid - 160;
        const float* wrow = in_w + p*2304 + eo*24;
        float s1 = 0.f, s2 = 0.f;
        #pragma unroll
        for (int dd = 0; dd < 24; dd++) {
            float w = wrow[dd];
            s1 += w*s_g[c0 + dd];
            s2 += w*s_bb[c0 + dd];
        }
        s_S1[eo] = s1; s_S2[eo] = s2;
    }
    __syncthreads();

    // ---- in_proj on RAW x, LN folded, 8e x 4j tiles ----
    for (int itx = tid; itx < 12*33; itx += 384) {
        int eg = itx/33, jg = itx%33;
        int e8 = eg*8, j4 = jg*4;
        float acc[8][4] = {};
        #pragma unroll
        for (int dd = 0; dd < 24; dd++) {
            float4 xv = *(const float4*)&s_x[(c0+dd)*PAD + j4];
            float4 w0 = *(const float4*)&s_wi[dd*96 + e8];
            float4 w1 = *(const float4*)&s_wi[dd*96 + e8 + 4];
            float wv[8] = {w0.x,w0.y,w0.z,w0.w,w1.x,w1.y,w1.z,w1.w};
            #pragma unroll
            for (int ee = 0; ee < 8; ee++) {
                acc[ee][0] += wv[ee]*xv.x; acc[ee][1] += wv[ee]*xv.y;
                acc[ee][2] += wv[ee]*xv.z; acc[ee][3] += wv[ee]*xv.w;
            }
        }
        int gl = l0 - 3 + j4;
        float muv[4] = { s_mu[j4], s_mu[j4+1], s_mu[j4+2], s_mu[j4+3] };
        float rsv[4] = { s_rs[j4], s_rs[j4+1], s_rs[j4+2], s_rs[j4+3] };
        #pragma unroll
        for (int ee = 0; ee < 8; ee++) {
            int eo = e8 + ee;
            float S1v = s_S1[eo], S2v = s_S2[eo];
            #pragma unroll
            for (int jj = 0; jj < 4; jj++) {
                int j = j4 + jj;
                if (j >= CHP) continue;
                float v = rsv[jj]*(acc[ee][jj] - muv[jj]*S1v) + S2v;
                if (gl + jj < 0) v = 0.f;
                if (eo < 48) s_xc[eo*PAD + j] = v;
                else if (j >= 3)
                    gZsh[((size_t)(be*48) + (eo-48))*LL + (size_t)(l0 + j - 3)] =
                        __float2half_rn(silu_f(v));
            }
        }
    }
    __syncthreads();

    // ---- conv(4) + silu, register staging ----
    {
        float4 ov[4];
        #pragma unroll
        for (int k = 0; k < 4; k++) {
            int q = tid + k*384;
            int d = q>>5, tq = (q&31)*4;
            float4 a  = *(const float4*)&s_xc[d*PAD + tq];
            float4 bq = *(const float4*)&s_xc[d*PAD + tq + 4];
            float w0 = s_cw[d*4+0], w1 = s_cw[d*4+1], w2 = s_cw[d*4+2], w3 = s_cw[d*4+3];
            float cb = s_cb[d];
            float o0 = cb + w0*a.x + w1*a.y + w2*a.z + w3*a.w;
            float o1 = cb + w0*a.y + w1*a.z + w2*a.w + w3*bq.x;
            float o2 = cb + w0*a.z + w1*a.w + w2*bq.x + w3*bq.y;
            float o3 = cb + w0*a.w + w1*bq.x + w2*bq.y + w3*bq.z;
            ov[k].x = silu_f(o0); ov[k].y = silu_f(o1);
            ov[k].z = silu_f(o2); ov[k].w = silu_f(o3);
        }
        __syncthreads();
        #pragma unroll
        for (int k = 0; k < 4; k++) {
            int q = tid + k*384;
            int d = q>>5, tq = (q&31)*4;
            *(float4*)&s_xc[d*PAD + tq] = ov[k];
        }
    }
    __syncthreads();

    // ---- x_proj: 2e2 x 4tok, 288 threads; gCm fused ----
    if (tid < 288) {
        int et = tid/32, tq4 = (tid%32)*4;
        float acc[2][4] = {};
        #pragma unroll
        for (int d = 0; d < 48; d++) {
            float2 wq = *(const float2*)&s_xw[d*20 + et*2];
            float4 xv = *(const float4*)&s_xc[d*PAD + tq4];
            acc[0][0]+=wq.x*xv.x; acc[0][1]+=wq.x*xv.y; acc[0][2]+=wq.x*xv.z; acc[0][3]+=wq.x*xv.w;
            acc[1][0]+=wq.y*xv.x; acc[1][1]+=wq.y*xv.y; acc[1][2]+=wq.y*xv.z; acc[1][3]+=wq.y*xv.w;
        }
        #pragma unroll
        for (int ee = 0; ee < 2; ee++) {
            int e2 = et*2 + ee;
            if (e2 < 2) {
                float4 st = {acc[ee][0], acc[ee][1], acc[ee][2], acc[ee][3]};
                *(float4*)&s_dtin[e2*PAD + tq4] = st;
            } else {
                int c = e2 - 2;
                int swz = ((tq4 >> 4) & 7) * 4;
                #pragma unroll
                for (int k = 0; k < 4; k++)
                    s_bt[(tq4+k)*20 + swz + c] = acc[ee][k];
                if (e2 >= 10) {
                    int cc = e2 - 10;
                    __half2* pC = (__half2*)&gCmh[(size_t)(be*8 + cc)*LL + l0 + tq4];
                    pC[0] = __floats2half2_rn(acc[ee][0], acc[ee][1]);
                    pC[1] = __floats2half2_rn(acc[ee][2], acc[ee][3]);
                }
            }
        }
    }
    __syncthreads();

    // ---- stateless two-pass scan: thread = (d, sub of 16 tokens) ----
    {
        int d = tid >> 3, sub = tid & 7;
        int t0 = sub * 16;
        const float* Aptr = A_log + p*384 + d*8;
        float A0 = -__expf(Aptr[0]);
        bool fast = true;
        #pragma unroll
        for (int s = 1; s < 8; s++) {
            float as = -__expf(Aptr[s]);
            if (fabsf(as - (float)(s+1)*A0) > 1e-4f*fabsf(as)) fast = false;
        }
        float dw0 = s_dtw[d*2], dw1 = s_dtw[d*2+1], bs0 = s_dtb[d];

        float h[8] = {0,0,0,0,0,0,0,0};
        float run = 0.f;
        // pass 1: h only (B loads only, no prefix array, no y0)
        #pragma unroll
        for (int k = 0; k < 4; k++) {
            float4 a0v = *(const float4*)&s_dtin[t0 + k*4];
            float4 a1v = *(const float4*)&s_dtin[PAD + t0 + k*4];
            float4 xcq = *(const float4*)&s_xc[d*PAD + t0 + k*4];
            float din0[4] = {a0v.x, a0v.y, a0v.z, a0v.w};
            float din1[4] = {a1v.x, a1v.y, a1v.z, a1v.w};
            float xcl[4]  = {xcq.x, xcq.y, xcq.z, xcq.w};
            #pragma unroll
            for (int j = 0; j < 4; j++) {
                int t = t0 + k*4 + j;
                float vv = bs0 + dw0*din0[j] + dw1*din1[j];
                float dv = (vv > 20.f) ? vv : __logf(1.f + __expf(vv));
                float dx = dv * xcl[j];
                run += dv;
                const float* rb = &s_bt[t*20 + sub*4];
                float4 b0 = *(const float4*)rb;
                float4 b1 = *(const float4*)(rb+4);
                if (fast) {
                    float q = __expf(dv * A0), pc = q;
                    h[0] = pc*h[0] + dx*b0.x; pc *= q;
                    h[1] = pc*h[1] + dx*b0.y; pc *= q;
                    h[2] = pc*h[2] + dx*b0.z; pc *= q;
                    h[3] = pc*h[3] + dx*b0.w; pc *= q;
                    h[4] = pc*h[4] + dx*b1.x; pc *= q;
                    h[5] = pc*h[5] + dx*b1.y; pc *= q;
                    h[6] = pc*h[6] + dx*b1.z; pc *= q;
                    h[7] = pc*h[7] + dx*b1.w;
                } else {
                    float Bv[8] = {b0.x,b0.y,b0.z,b0.w,b1.x,b1.y,b1.z,b1.w};
                    #pragma unroll
                    for (int s = 0; s < 8; s++) {
                        float as = -__expf(Aptr[s]);
                        h[s] = __expf(dv*as)*h[s] + dx*Bv[s];
                    }
                }
            }
        }

        // Kogge-Stone inclusive scan over 8 subs
        float S = run;
        #pragma unroll
        for (int st = 1; st < 8; st <<= 1) {
            float Sp = __shfl_up_sync(0xFFFFFFFFu, S, st, 8);
            float hp[8];
            #pragma unroll
            for (int s = 0; s < 8; s++) hp[s] = __shfl_up_sync(0xFFFFFFFFu, h[s], st, 8);
            if (sub >= st) {
                if (fast) {
                    float q = __expf(S * A0), pc = q;
                    #pragma unroll
                    for (int s = 0; s < 8; s++) { h[s] = pc*hp[s] + h[s]; pc *= q; }
                } else {
                    #pragma unroll
                    for (int s = 0; s < 8; s++) {
                        float as = -__expf(Aptr[s]);
                        h[s] = __expf(S*as)*hp[s] + h[s];
                    }
                }
                S += Sp;
            }
        }
        if (sub == 7) {
            #pragma unroll
            for (int s = 0; s < 8; s++)
                gHend[(size_t)(be*NCHK + ck)*384 + d*8 + s] = h[s];
            gSsum[(size_t)(be*NCHK + ck)*48 + d] = S;
        }
        // exclusive state at sub start
        float Sex;
        {
            float Hex[8];
            #pragma unroll
            for (int s = 0; s < 8; s++) Hex[s] = __shfl_up_sync(0xFFFFFFFFu, h[s], 1, 8);
            Sex = __shfl_up_sync(0xFFFFFFFFu, S, 1, 8);
            if (sub == 0) {
                Sex = 0.f;
                #pragma unroll
                for (int s = 0; s < 8; s++) Hex[s] = 0.f;
            }
            #pragma unroll
            for (int s = 0; s < 8; s++) h[s] = Hex[s];
        }

        // pass 2: full recurrence from sub-carry state; recompute dt/q
        float Dpd = s_Dp[d];
        size_t gb = (size_t)(be*48 + d)*LL + l0 + t0;
        float run2 = Sex;
        #pragma unroll
        for (int k = 0; k < 4; k++) {
            float4 a0v = *(const float4*)&s_dtin[t0 + k*4];
            float4 a1v = *(const float4*)&s_dtin[PAD + t0 + k*4];
            float4 xcq = *(const float4*)&s_xc[d*PAD + t0 + k*4];
            float din0[4] = {a0v.x, a0v.y, a0v.z, a0v.w};
            float din1[4] = {a1v.x, a1v.y, a1v.z, a1v.w};
            float xcl[4]  = {xcq.x, xcq.y, xcq.z, xcq.w};
            float yo[4], so[4];
            #pragma unroll
            for (int j = 0; j < 4; j++) {
                int t = t0 + k*4 + j;
                float vv = bs0 + dw0*din0[j] + dw1*din1[j];
                float dv = (vv > 20.f) ? vv : __logf(1.f + __expf(vv));
                float dx = dv * xcl[j];
                run2 += dv;
                const float* rb = &s_bt[t*20 + sub*4];
                float4 b0 = *(const float4*)rb;
                float4 b1 = *(const float4*)(rb+4);
                float4 cv0 = *(const float4*)(rb+8);
                float4 cv1 = *(const float4*)(rb+12);
                float y = 0.f;
                if (fast) {
                    float q = __expf(dv * A0), pc = q;
                    h[0] = pc*h[0] + dx*b0.x; y += h[0]*cv0.x; pc *= q;
                    h[1] = pc*h[1] + dx*b0.y; y += h[1]*cv0.y; pc *= q;
                    h[2] = pc*h[2] + dx*b0.z; y += h[2]*cv0.z; pc *= q;
                    h[3] = pc*h[3] + dx*b0.w; y += h[3]*cv0.w; pc *= q;
                    h[4] = pc*h[4] + dx*b1.x; y += h[4]*cv1.x; pc *= q;
                    h[5] = pc*h[5] + dx*b1.y; y += h[5]*cv1.y; pc *= q;
                    h[6] = pc*h[6] + dx*b1.z; y += h[6]*cv1.z; pc *= q;
                    h[7] = pc*h[7] + dx*b1.w; y += h[7]*cv1.w;
                } else {
                    float Bv[8] = {b0.x,b0.y,b0.z,b0.w,b1.x,b1.y,b1.z,b1.w};
                    float Cv[8] = {cv0.x,cv0.y,cv0.z,cv0.w,cv1.x,cv1.y,cv1.z,cv1.w};
                    #pragma unroll
                    for (int s = 0; s < 8; s++) {
                        float as = -__expf(Aptr[s]);
                        h[s] = __expf(dv*as)*h[s] + dx*Bv[s];
                        y += h[s]*Cv[s];
                    }
                }
                yo[j] = y + xcl[j]*Dpd;
                so[j] = run2;
            }
            __half2* pY = (__half2*)&gY0h[gb + k*4];
            pY[0] = __floats2half2_rn(yo[0], yo[1]);
            pY[1] = __floats2half2_rn(yo[2], yo[3]);
            float4 sq = {so[0],so[1],so[2],so[3]};
            *(float4*)&gSdt[gb + k*4] = sq;
        }
    }
}

// ---------------- K2: parallel carry combine ----------------
__global__ __launch_bounds__(384) void k_combine(const float* __restrict__ A_log, int iter)
{
    int be = blockIdx.x, e = be & 1, p = 2*iter + e;
    int grp = blockIdx.y;
    int tid = threadIdx.x;
    int elem = grp*48 + (tid >> 3);
    int sub = tid & 7;
    int d = elem >> 3;
    float A_ds = -expf(A_log[p*384 + elem]);
    int ck0 = sub * 32;

    float hrun = 0.f, Ssum = 0.f;
    for (int k = 0; k < 32; k++) {
        int ck = ck0 + k;
        float hv = gHend[(size_t)(be*NCHK + ck)*384 + elem];
        float Sv = gSsum[(size_t)(be*NCHK + ck)*48 + d];
        hrun = __expf(Sv*A_ds)*hrun + hv;
        Ssum += Sv;
    }
    float H = hrun, S = Ssum;
    #pragma unroll
    for (int st = 1; st < 8; st <<= 1) {
        float Hp = __shfl_up_sync(0xFFFFFFFFu, H, st, 8);
        float Sp = __shfl_up_sync(0xFFFFFFFFu, S, st, 8);
        if (sub >= st) { H = __expf(S*A_ds)*Hp + H; S += Sp; }
    }
    float Hexc = __shfl_up_sync(0xFFFFFFFFu, H, 1, 8);
    if (sub == 0) Hexc = 0.f;
    hrun = Hexc;
    for (int k = 0; k < 32; k++) {
        int ck = ck0 + k;
        gH0c[(size_t)(be*NCHK + ck)*384 + elem] = hrun;
        float hv = gHend[(size_t)(be*NCHK + ck)*384 + elem];
        float Sv = gSsum[(size_t)(be*NCHK + ck)*48 + d];
        hrun = __expf(Sv*A_ds)*hrun + hv;
    }
}

// ---------------- K3: correction + gate + out_proj + residual ----------------
__global__ __launch_bounds__(384, 3) void k_output(
    const float* __restrict__ A_log, const float* __restrict__ out_w,
    const float* __restrict__ xext, int useX, int iter)
{
    int ck = blockIdx.x, e = blockIdx.y, b = blockIdx.z;
    int p = 2*iter + e, be = b*2 + e, l0 = ck*CHN, tid = threadIdx.x;

    extern __shared__ float sm[];
    float* s_y    = sm;              // [48][128]
    float* s_Cm   = s_y  + 48*128;   // [8][128]
    float* s_h0   = s_Cm + 8*128;    // [384]
    float* s_A    = s_h0 + 384;      // [384]
    float* s_ow   = s_A  + 384;      // [48][24] transposed
    float* s_fast = s_ow + 1152;     // [48]

    s_h0[tid] = gH0c[(size_t)(be*NCHK + ck)*384 + tid];
    s_A[tid]  = -__expf(A_log[p*384 + tid]);
    for (int i = tid; i < 1152; i += 384) {
        int m = i/48, d = i%48;
        s_ow[d*24 + m] = out_w[p*1152 + i];
    }
    for (int i = tid; i < 8*32; i += 384) {
        int ss = i>>5, tq = (i&31)*4;
        const __half2* src = (const __half2*)&gCmh[(size_t)(be*8 + ss)*LL + l0 + tq];
        float2 a = __half22float2(src[0]), bq = __half22float2(src[1]);
        float4 st = {a.x, a.y, bq.x, bq.y};
        *(float4*)&s_Cm[ss*128 + tq] = st;
    }
    if (tid < 48) {
        float a0 = -__expf(A_log[p*384 + tid*8]);
        float ok = 1.f;
        #pragma unroll
        for (int s = 1; s < 8; s++) {
            float as = -__expf(A_log[p*384 + tid*8 + s]);
            if (fabsf(as - (float)(s+1)*a0) > 1e-4f * fabsf(as)) ok = 0.f;
        }
        s_fast[tid] = ok;
    }
    __syncthreads();

    size_t baseF = (size_t)(be*48)*LL + l0;
    for (int itx = tid; itx < 48*32; itx += 384) {
        int d = itx>>5, tq = (itx&31)*4;
        size_t g = baseF + (size_t)d*LL + tq;
        float4 sd4 = *(const float4*)&gSdt[g];
        const __half2* pY = (const __half2*)&gY0h[g];
        const __half2* pZ = (const __half2*)&gZsh[g];
        float2 ya = __half22float2(pY[0]), yb = __half22float2(pY[1]);
        float2 za = __half22float2(pZ[0]), zb = __half22float2(pZ[1]);
        float acc[4] = {ya.x, ya.y, yb.x, yb.y};
        if (s_fast[d] != 0.f) {
            float A0d = s_A[d*8];
            float r0 = __expf(sd4.x*A0d), r1 = __expf(sd4.y*A0d);
            float r2 = __expf(sd4.z*A0d), r3 = __expf(sd4.w*A0d);
            float p0 = r0, p1 = r1, p2 = r2, p3 = r3;
            #pragma unroll
            for (int s = 0; s < 8; s++) {
                float4 cm = *(const float4*)&s_Cm[s*128 + tq];
                float hh = s_h0[d*8 + s];
                acc[0] += cm.x*p0*hh; acc[1] += cm.y*p1*hh;
                acc[2] += cm.z*p2*hh; acc[3] += cm.w*p3*hh;
                p0 *= r0; p1 *= r1; p2 *= r2; p3 *= r3;
            }
        } else {
            float sdv[4] = {sd4.x, sd4.y, sd4.z, sd4.w};
            #pragma unroll
            for (int s = 0; s < 8; s++) {
                float4 cm = *(const float4*)&s_Cm[s*128 + tq];
                float hh = s_h0[d*8 + s];
                float As = s_A[d*8 + s];
                acc[0] += cm.x*__expf(sdv[0]*As)*hh;
                acc[1] += cm.y*__expf(sdv[1]*As)*hh;
                acc[2] += cm.z*__expf(sdv[2]*As)*hh;
                acc[3] += cm.w*__expf(sdv[3]*As)*hh;
            }
        }
        float4 yq = {acc[0]*za.x, acc[1]*za.y, acc[2]*zb.x, acc[3]*zb.y};
        *(float4*)&s_y[d*128 + tq] = yq;
    }
    __syncthreads();

    const float* resb = (useX ? xext : (const float*)gXf);
    if (tid < 192) {
        int mt = tid/32, tq = (tid%32)*4;
        float acc[4][4] = {};
        #pragma unroll
        for (int dd = 0; dd < 48; dd++) {
            float4 wq = *(const float4*)&s_ow[dd*24 + mt*4];
            float4 yv = *(const float4*)&s_y[dd*128 + tq];
            acc[0][0]+=wq.x*yv.x; acc[0][1]+=wq.x*yv.y; acc[0][2]+=wq.x*yv.z; acc[0][3]+=wq.x*yv.w;
            acc[1][0]+=wq.y*yv.x; acc[1][1]+=wq.y*yv.y; acc[1][2]+=wq.y*yv.z; acc[1][3]+=wq.y*yv.w;
            acc[2][0]+=wq.z*yv.x; acc[2][1]+=wq.z*yv.y; acc[2][2]+=wq.z*yv.z; acc[2][3]+=wq.z*yv.w;
            acc[3][0]+=wq.w*yv.x; acc[3][1]+=wq.w*yv.y; acc[3][2]+=wq.w*yv.z; acc[3][3]+=wq.w*yv.w;
        }
        #pragma unroll
        for (int mm = 0; mm < 4; mm++) {
            int m = mt*4 + mm;
            int c = e*24 + m;
            size_t rowb = (size_t)(b*48 + c)*LL;
            if (e == 0) {
                size_t o = rowb + l0 + tq;
                float4 r = *(const float4*)&resb[o];
                float4 st = {acc[mm][0]+r.x, acc[mm][1]+r.y, acc[mm][2]+r.z, acc[mm][3]+r.w};
                *(float4*)&gYf[o] = st;
            } else {
                size_t o = rowb + (size_t)(LL - 4 - l0 - tq);
                float4 r = *(const float4*)&resb[o];
                float4 st = {acc[mm][3]+r.x, acc[mm][2]+r.y, acc[mm][1]+r.z, acc[mm][0]+r.w};
                *(float4*)&gYf[o] = st;
            }
        }
    }
}

#define SM_F ((2*48*PAD + 2304 + 192 + 48 + 960 + 96 + 48 + 48 + 48 + 48 + 132 + 132 + 96 + 96 + 768) * 4)
#define SM_O ((48*128 + 8*128 + 384 + 384 + 1152 + 48) * 4)

extern "C" void kernel_launch(void* const* d_in, const int* in_sizes, int n_in,
                              void* d_out, int out_size)
{
    const float* x       = (const float*)d_in[0];
    const float* ln_g    = (const float*)d_in[1];
    const float* ln_b    = (const float*)d_in[2];
    const float* in_w    = (const float*)d_in[3];
    const float* conv_w  = (const float*)d_in[4];
    const float* conv_b  = (const float*)d_in[5];
    const float* xproj_w = (const float*)d_in[6];
    const float* dt_w    = (const float*)d_in[7];
    const float* dt_b    = (const float*)d_in[8];
    const float* A_log   = (const float*)d_in[9];
    const float* Dp      = (const float*)d_in[10];
    const float* out_w   = (const float*)d_in[11];
    float* out = (float*)d_out;

    cudaFuncSetAttribute(k_features, cudaFuncAttributeMaxDynamicSharedMemorySize, SM_F);
    cudaFuncSetAttribute(k_output,   cudaFuncAttributeMaxDynamicSharedMemorySize, SM_O);

    dim3 pg(8, 96), pb(32, 32);
    for (int it = 0; it < 3; ++it) {
        int useX = (it == 0) ? 1 : 0;
        k_features<<<dim3(NCHK,2,2), 384, SM_F>>>(ln_g, ln_b, in_w, conv_w, conv_b,
                                                  xproj_w, dt_w, dt_b, A_log, Dp,
                                                  x, useX, it);
        k_combine<<<dim3(4,8), 384>>>(A_log, it);
        k_output<<<dim3(NCHK,2,2), 384, SM_O>>>(A_log, out_w, x, useX, it);
        if (it < 2) k_rot<<<pg, pb>>>();
        else        k_final<<<pg, pb>>>(out, x);
    }
}

// round 16
// speedup vs baseline: 1.7466x; 1.7466x over previous
#include <cuda_runtime.h>
#include <cuda_fp16.h>
#include <math.h>

#define LL   32768
#define CHN  128
#define NCHK 256
#define CHP  131
#define PAD  132

// ---------------- static device scratch ----------------
__device__ float  gXf [2*48*LL];
__device__ float  gYf [2*48*LL];
__device__ __half gY0h[4*48*LL];
__device__ float  gSdt[4*48*LL];
__device__ __half gZsh[4*48*LL];
__device__ __half gCmh[4*8*LL];
__device__ float  gHend[4*NCHK*384];
__device__ float  gSsum[4*NCHK*48];
__device__ float  gH0c [4*NCHK*384];

__device__ __forceinline__ float silu_f(float v) { return __fdividef(v, 1.f + __expf(-v)); }

// ---------------- fused rotation ----------------
__global__ void k_rot()
{
    __shared__ float tile[4][32][33];
    int bc = blockIdx.y, f0 = blockIdx.x * 4;
    int tx = threadIdx.x, ty = threadIdx.y;
    const float* s = gYf + (size_t)bc * LL;
    float* d = gXf + (size_t)bc * LL;
    #pragma unroll
    for (int k = 0; k < 4; k++)
        tile[k][ty][tx] = s[ty*1024 + (f0+k)*32 + tx];
    __syncthreads();
    #pragma unroll
    for (int k = 0; k < 4; k++)
        d[(f0+k)*1024 + ty*32 + tx] = tile[k][tx][ty];
}

// ---------------- final ----------------
__global__ void k_final(float* extd, const float* __restrict__ xext)
{
    __shared__ float tile[4][32][33];
    int bc = blockIdx.y, f0 = blockIdx.x * 4;
    int tx = threadIdx.x, ty = threadIdx.y;
    const float* s = gYf + (size_t)bc * LL;
    const float* xb = xext + (size_t)bc * LL;
    float* d = extd + (size_t)bc * LL;
    #pragma unroll
    for (int k = 0; k < 4; k++)
        tile[k][ty][tx] = s[ty*1024 + (f0+k)*32 + tx];
    __syncthreads();
    #pragma unroll
    for (int k = 0; k < 4; k++) {
        int o = (f0+k)*1024 + ty*32 + tx;
        d[o] = tile[k][tx][ty] + xb[o];
    }
}

// ---------------- K1: features (LN folded) + register-resident scan ----------------
__global__ __launch_bounds__(384, 2) void k_features(
    const float* __restrict__ ln_g, const float* __restrict__ ln_b,
    const float* __restrict__ in_w, const float* __restrict__ conv_w,
    const float* __restrict__ conv_b, const float* __restrict__ xproj_w,
    const float* __restrict__ dt_w, const float* __restrict__ dt_b,
    const float* __restrict__ A_log, const float* __restrict__ Dpar,
    const float* __restrict__ xext, int useX, int iter)
{
    int ck = blockIdx.x, e = blockIdx.y, b = blockIdx.z;
    int p = 2*iter + e, be = b*2 + e, l0 = ck*CHN, tid = threadIdx.x;

    extern __shared__ float sm[];
    float* s_x    = sm;                 // [48][PAD] RAW x (dead after in_proj)
    float* s_dtin = s_x;                // ALIAS [2][PAD]
    float* s_bt   = s_x + 264;          // ALIAS [2592]
    float* s_xc   = sm + 48*PAD;        // [48][PAD]
    float* s_wi   = s_xc + 48*PAD;      // [24][96]
    float* s_cw   = s_wi + 2304;        // [48][4]
    float* s_cb   = s_cw + 192;
    float* s_xw   = s_cb + 48;          // [48][20]
    float* s_dtw  = s_xw + 960;
    float* s_dtb  = s_dtw + 96;
    float* s_g    = s_dtb + 48;
    float* s_bb   = s_g + 48;
    float* s_Dp   = s_bb + 48;
    float* s_mu   = s_Dp + 48;          // [132]
    float* s_rs   = s_mu + 132;         // [132]
    float* s_S1   = s_rs + 132;         // [96]
    float* s_S2   = s_S1 + 96;          // [96]

    // ---- loads ----
    for (int i = tid; i < 2304; i += 384) {
        int eo = i/24, dd = i%24;
        s_wi[dd*96 + eo] = in_w[p*2304 + i];
    }
    for (int i = tid; i < 192; i += 384) s_cw[i] = conv_w[p*192 + i];
    for (int i = tid; i < 864; i += 384) {
        int e2 = i/48, d = i%48;
        s_xw[d*20 + e2] = xproj_w[p*864 + i];
    }
    for (int i = tid; i < 96; i += 384) s_xw[(i>>1)*20 + 18 + (i&1)] = 0.f;
    for (int i = tid; i < 96; i += 384) s_dtw[i] = dt_w[p*96 + i];
    if (tid < 48) {
        s_cb[tid]  = conv_b[p*48 + tid];  s_dtb[tid] = dt_b[p*48 + tid];
        s_g[tid]   = ln_g[iter*48 + tid]; s_bb[tid]  = ln_b[iter*48 + tid];
        s_Dp[tid]  = Dpar[p*48 + tid];
    }
    const float* xfb = (useX ? xext : (const float*)gXf) + (size_t)b*48*LL;
    for (int i = tid; i < 48*PAD; i += 384) {
        int c = i/PAD, j = i%PAD;
        int l = l0 - 3 + j;
        float v = 0.f;
        if (j < CHP && l >= 0) {
            int t = (e == 0) ? l : (LL - 1 - l);
            v = xfb[(size_t)c*LL + t];
        }
        s_x[i] = v;
    }
    __syncthreads();

    // ---- phase A: LN stats + folded-weight sums ----
    int c0 = e*24;
    if (tid < CHP) {
        int j = tid;
        float su = 0.f, sq = 0.f;
        #pragma unroll
        for (int c = 0; c < 48; c++) { float xv = s_x[c*PAD + j]; su += xv; sq += xv*xv; }
        float mu = su*(1.f/48.f);
        float var = sq*(1.f/48.f) - mu*mu;
        s_mu[j] = mu;
        s_rs[j] = rsqrtf(var + 1e-5f);
    }
    if (tid >= 288) {
        int eo = tid - 288;
        const float* wrow = in_w + p*2304 + eo*24;
        float s1 = 0.f, s2 = 0.f;
        #pragma unroll
        for (int dd = 0; dd < 24; dd++) {
            float w = wrow[dd];
            s1 += w*s_g[c0 + dd];
            s2 += w*s_bb[c0 + dd];
        }
        s_S1[eo] = s1; s_S2[eo] = s2;
    }
    for (int i = tid; i < 2304; i += 384) {
        int dd = i/96;
        s_wi[i] *= s_g[c0 + dd];
    }
    __syncthreads();

    // ---- in_proj on RAW x, LN folded, 8e x 4j tiles ----
    for (int itx = tid; itx < 12*33; itx += 384) {
        int eg = itx/33, jg = itx%33;
        int e8 = eg*8, j4 = jg*4;
        float acc[8][4] = {};
        #pragma unroll
        for (int dd = 0; dd < 24; dd++) {
            float4 xv = *(const float4*)&s_x[(c0+dd)*PAD + j4];
            float4 w0 = *(const float4*)&s_wi[dd*96 + e8];
            float4 w1 = *(const float4*)&s_wi[dd*96 + e8 + 4];
            float wv[8] = {w0.x,w0.y,w0.z,w0.w,w1.x,w1.y,w1.z,w1.w};
            #pragma unroll
            for (int ee = 0; ee < 8; ee++) {
                acc[ee][0] += wv[ee]*xv.x; acc[ee][1] += wv[ee]*xv.y;
                acc[ee][2] += wv[ee]*xv.z; acc[ee][3] += wv[ee]*xv.w;
            }
        }
        int gl = l0 - 3 + j4;
        float muv[4] = { s_mu[j4], s_mu[j4+1], s_mu[j4+2], s_mu[j4+3] };
        float rsv[4] = { s_rs[j4], s_rs[j4+1], s_rs[j4+2], s_rs[j4+3] };
        #pragma unroll
        for (int ee = 0; ee < 8; ee++) {
            int eo = e8 + ee;
            float S1v = s_S1[eo], S2v = s_S2[eo];
            #pragma unroll
            for (int jj = 0; jj < 4; jj++) {
                int j = j4 + jj;
                if (j >= CHP) continue;
                float v = rsv[jj]*(acc[ee][jj] - muv[jj]*S1v) + S2v;
                if (gl + jj < 0) v = 0.f;
                if (eo < 48) s_xc[eo*PAD + j] = v;
                else if (j >= 3)
                    gZsh[((size_t)(be*48) + (eo-48))*LL + (size_t)(l0 + j - 3)] =
                        __float2half_rn(silu_f(v));
            }
        }
    }
    __syncthreads();

    // ---- causal conv(4) + silu, vectorized, in place via register staging ----
    {
        float4 ov[4];
        #pragma unroll
        for (int k = 0; k < 4; k++) {
            int q = tid + k*384;
            int d = q>>5, tq = (q&31)*4;
            float4 a  = *(const float4*)&s_xc[d*PAD + tq];
            float4 bq = *(const float4*)&s_xc[d*PAD + tq + 4];
            float w0 = s_cw[d*4+0], w1 = s_cw[d*4+1], w2 = s_cw[d*4+2], w3 = s_cw[d*4+3];
            float cb = s_cb[d];
            float o0 = cb + w0*a.x + w1*a.y + w2*a.z + w3*a.w;
            float o1 = cb + w0*a.y + w1*a.z + w2*a.w + w3*bq.x;
            float o2 = cb + w0*a.z + w1*a.w + w2*bq.x + w3*bq.y;
            float o3 = cb + w0*a.w + w1*bq.x + w2*bq.y + w3*bq.z;
            ov[k].x = silu_f(o0); ov[k].y = silu_f(o1);
            ov[k].z = silu_f(o2); ov[k].w = silu_f(o3);
        }
        __syncthreads();
        #pragma unroll
        for (int k = 0; k < 4; k++) {
            int q = tid + k*384;
            int d = q>>5, tq = (q&31)*4;
            *(float4*)&s_xc[d*PAD + tq] = ov[k];
        }
    }
    __syncthreads();

    // ---- x_proj: 2e2 x 4tok tiles, 288 threads, float2 weights ----
    if (tid < 288) {
        int et = tid/32, tq4 = (tid%32)*4;
        float acc[2][4] = {};
        #pragma unroll
        for (int d = 0; d < 48; d++) {
            float2 wq = *(const float2*)&s_xw[d*20 + et*2];
            float4 xv = *(const float4*)&s_xc[d*PAD + tq4];
            acc[0][0]+=wq.x*xv.x; acc[0][1]+=wq.x*xv.y; acc[0][2]+=wq.x*xv.z; acc[0][3]+=wq.x*xv.w;
            acc[1][0]+=wq.y*xv.x; acc[1][1]+=wq.y*xv.y; acc[1][2]+=wq.y*xv.z; acc[1][3]+=wq.y*xv.w;
        }
        #pragma unroll
        for (int ee = 0; ee < 2; ee++) {
            int e2 = et*2 + ee;
            if (e2 < 2) {
                float4 st = {acc[ee][0], acc[ee][1], acc[ee][2], acc[ee][3]};
                *(float4*)&s_dtin[e2*PAD + tq4] = st;
            } else {
                int c = e2 - 2;
                int swz = ((tq4 >> 4) & 7) * 4;
                #pragma unroll
                for (int k = 0; k < 4; k++)
                    s_bt[(tq4+k)*20 + swz + c] = acc[ee][k];
            }
        }
    }
    __syncthreads();

    // gCm write (fp16, reads s_bt only)
    for (int itx = tid; itx < 8*CHN; itx += 384) {
        int ss = itx>>7, t = itx&127;
        gCmh[(size_t)(be*8 + ss)*LL + l0 + t] =
            __float2half_rn(s_bt[t*20 + ((t>>4)&7)*4 + 8 + ss]);
    }

    // ---- register-resident hierarchical scan: thread = (d, sub of 16 tokens) ----
    {
        int d = tid >> 3, sub = tid & 7;
        int t0 = sub * 16;
        const float* Aptr = A_log + p*384 + d*8;
        float A0 = -__expf(Aptr[0]);
        bool fast = true;
        #pragma unroll
        for (int s = 1; s < 8; s++) {
            float as = -__expf(Aptr[s]);
            if (fabsf(as - (float)(s+1)*A0) > 1e-4f*fabsf(as)) fast = false;
        }

        // dt = softplus(dt_in @ dtw^T + dtb)
        float dtv[16];
        {
            float w0 = s_dtw[d*2], w1 = s_dtw[d*2+1], bs0 = s_dtb[d];
            #pragma unroll
            for (int k = 0; k < 4; k++) {
                float4 a0v = *(const float4*)&s_dtin[t0 + k*4];
                float4 a1v = *(const float4*)&s_dtin[PAD + t0 + k*4];
                float vv0 = bs0 + w0*a0v.x + w1*a1v.x;
                float vv1 = bs0 + w0*a0v.y + w1*a1v.y;
                float vv2 = bs0 + w0*a0v.z + w1*a1v.z;
                float vv3 = bs0 + w0*a0v.w + w1*a1v.w;
                dtv[k*4+0] = (vv0 > 20.f) ? vv0 : __logf(1.f + __expf(vv0));
                dtv[k*4+1] = (vv1 > 20.f) ? vv1 : __logf(1.f + __expf(vv1));
                dtv[k*4+2] = (vv2 > 20.f) ? vv2 : __logf(1.f + __expf(vv2));
                dtv[k*4+3] = (vv3 > 20.f) ? vv3 : __logf(1.f + __expf(vv3));
            }
        }

        float h[8] = {0,0,0,0,0,0,0,0};
        float y0l[16];
        float run = 0.f;
        if (fast) {
            #pragma unroll
            for (int k = 0; k < 4; k++) {
                float4 xcq = *(const float4*)&s_xc[d*PAD + t0 + k*4];
                float xcl[4] = {xcq.x, xcq.y, xcq.z, xcq.w};
                #pragma unroll
                for (int j = 0; j < 4; j++) {
                    int tt = k*4 + j, t = t0 + tt;
                    float dv = dtv[tt];
                    float dx = dv * xcl[j];
                    const float* rb = &s_bt[t*20 + sub*4];
                    float4 b0 = *(const float4*)rb;
                    float4 b1 = *(const float4*)(rb+4);
                    float4 cv0 = *(const float4*)(rb+8);
                    float4 cv1 = *(const float4*)(rb+12);
                    float q = __expf(dv * A0), pc = q;
                    float y0 = 0.f;
                    h[0] = pc*h[0] + dx*b0.x; y0 += h[0]*cv0.x; pc *= q;
                    h[1] = pc*h[1] + dx*b0.y; y0 += h[1]*cv0.y; pc *= q;
                    h[2] = pc*h[2] + dx*b0.z; y0 += h[2]*cv0.z; pc *= q;
                    h[3] = pc*h[3] + dx*b0.w; y0 += h[3]*cv0.w; pc *= q;
                    h[4] = pc*h[4] + dx*b1.x; y0 += h[4]*cv1.x; pc *= q;
                    h[5] = pc*h[5] + dx*b1.y; y0 += h[5]*cv1.y; pc *= q;
                    h[6] = pc*h[6] + dx*b1.z; y0 += h[6]*cv1.z; pc *= q;
                    h[7] = pc*h[7] + dx*b1.w; y0 += h[7]*cv1.w;
                    y0l[tt] = y0;
                    run += dv;
                    dtv[tt] = run;
                }
            }
        } else {
            #pragma unroll
            for (int k = 0; k < 4; k++) {
                float4 xcq = *(const float4*)&s_xc[d*PAD + t0 + k*4];
                float xcl[4] = {xcq.x, xcq.y, xcq.z, xcq.w};
                #pragma unroll
                for (int j = 0; j < 4; j++) {
                    int tt = k*4 + j, t = t0 + tt;
                    float dv = dtv[tt];
                    float dx = dv * xcl[j];
                    const float* rb = &s_bt[t*20 + sub*4];
                    float4 b0 = *(const float4*)rb;
                    float4 b1 = *(const float4*)(rb+4);
                    float4 cv0 = *(const float4*)(rb+8);
                    float4 cv1 = *(const float4*)(rb+12);
                    float Bv[8] = {b0.x,b0.y,b0.z,b0.w,b1.x,b1.y,b1.z,b1.w};
                    float Cv[8] = {cv0.x,cv0.y,cv0.z,cv0.w,cv1.x,cv1.y,cv1.z,cv1.w};
                    float y0 = 0.f;
                    #pragma unroll
                    for (int s = 0; s < 8; s++) {
                        float as = -__expf(Aptr[s]);
                        h[s] = __expf(dv*as)*h[s] + dx*Bv[s];
                        y0 += h[s]*Cv[s];
                    }
                    y0l[tt] = y0;
                    run += dv;
                    dtv[tt] = run;
                }
            }
        }

        // Kogge-Stone inclusive scan over 8 subs
        float S = run;
        #pragma unroll
        for (int st = 1; st < 8; st <<= 1) {
            float Sp = __shfl_up_sync(0xFFFFFFFFu, S, st, 8);
            float hp[8];
            #pragma unroll
            for (int s = 0; s < 8; s++) hp[s] = __shfl_up_sync(0xFFFFFFFFu, h[s], st, 8);
            if (sub >= st) {
                if (fast) {
                    float q = __expf(S * A0), pc = q;
                    #pragma unroll
                    for (int s = 0; s < 8; s++) { h[s] = pc*hp[s] + h[s]; pc *= q; }
                } else {
                    #pragma unroll
                    for (int s = 0; s < 8; s++) {
                        float as = -__expf(Aptr[s]);
                        h[s] = __expf(S*as)*hp[s] + h[s];
                    }
                }
                S += Sp;
            }
        }
        float Hex[8], Sex;
        #pragma unroll
        for (int s = 0; s < 8; s++) Hex[s] = __shfl_up_sync(0xFFFFFFFFu, h[s], 1, 8);
        Sex = __shfl_up_sync(0xFFFFFFFFu, S, 1, 8);
        if (sub == 0) {
            Sex = 0.f;
            #pragma unroll
            for (int s = 0; s < 8; s++) Hex[s] = 0.f;
        }
        if (sub == 7) {
            #pragma unroll
            for (int s = 0; s < 8; s++)
                gHend[(size_t)(be*NCHK + ck)*384 + d*8 + s] = h[s];
            gSsum[(size_t)(be*NCHK + ck)*48 + d] = S;
        }

        // pass 2: carry correction + fp16 gY0 stores, fp32 gSdt stores
        float Dpd = s_Dp[d];
        size_t gb = (size_t)(be*48 + d)*LL + l0 + t0;
        #pragma unroll
        for (int k = 0; k < 4; k++) {
            float4 xcq = *(const float4*)&s_xc[d*PAD + t0 + k*4];
            float xcl[4] = {xcq.x, xcq.y, xcq.z, xcq.w};
            float yo[4], so[4];
            #pragma unroll
            for (int j = 0; j < 4; j++) {
                int tt = k*4 + j, t = t0 + tt;
                float Sloc = dtv[tt];
                float y = y0l[tt];
                const float* rb = &s_bt[t*20 + sub*4 + 8];
                float4 cv0 = *(const float4*)rb;
                float4 cv1 = *(const float4*)(rb+4);
                if (fast) {
                    float r = __expf(Sloc * A0), pc = r;
                    y += cv0.x*pc*Hex[0]; pc *= r;
                    y += cv0.y*pc*Hex[1]; pc *= r;
                    y += cv0.z*pc*Hex[2]; pc *= r;
                    y += cv0.w*pc*Hex[3]; pc *= r;
                    y += cv1.x*pc*Hex[4]; pc *= r;
                    y += cv1.y*pc*Hex[5]; pc *= r;
                    y += cv1.z*pc*Hex[6]; pc *= r;
                    y += cv1.w*pc*Hex[7];
                } else {
                    float Cv[8] = {cv0.x,cv0.y,cv0.z,cv0.w,cv1.x,cv1.y,cv1.z,cv1.w};
                    #pragma unroll
                    for (int s = 0; s < 8; s++) {
                        float as = -__expf(Aptr[s]);
                        y += Cv[s]*__expf(Sloc*as)*Hex[s];
                    }
                }
                yo[j] = y + xcl[j]*Dpd;
                so[j] = Sloc + Sex;
            }
            __half2* pY = (__half2*)&gY0h[gb + k*4];
            pY[0] = __floats2half2_rn(yo[0], yo[1]);
            pY[1] = __floats2half2_rn(yo[2], yo[3]);
            float4 sq = {so[0],so[1],so[2],so[3]};
            *(float4*)&gSdt[gb + k*4] = sq;
        }
    }
}

// ---------------- K2: parallel carry combine ----------------
__global__ __launch_bounds__(384) void k_combine(const float* __restrict__ A_log, int iter)
{
    int be = blockIdx.x, e = be & 1, p = 2*iter + e;
    int grp = blockIdx.y;
    int tid = threadIdx.x;
    int elem = grp*48 + (tid >> 3);
    int sub = tid & 7;
    int d = elem >> 3;
    float A_ds = -expf(A_log[p*384 + elem]);
    int ck0 = sub * 32;

    float hrun = 0.f, Ssum = 0.f;
    for (int k = 0; k < 32; k++) {
        int ck = ck0 + k;
        float hv = gHend[(size_t)(be*NCHK + ck)*384 + elem];
        float Sv = gSsum[(size_t)(be*NCHK + ck)*48 + d];
        hrun = __expf(Sv*A_ds)*hrun + hv;
        Ssum += Sv;
    }
    float H = hrun, S = Ssum;
    #pragma unroll
    for (int st = 1; st < 8; st <<= 1) {
        float Hp = __shfl_up_sync(0xFFFFFFFFu, H, st, 8);
        float Sp = __shfl_up_sync(0xFFFFFFFFu, S, st, 8);
        if (sub >= st) { H = __expf(S*A_ds)*Hp + H; S += Sp; }
    }
    float Hexc = __shfl_up_sync(0xFFFFFFFFu, H, 1, 8);
    if (sub == 0) Hexc = 0.f;
    hrun = Hexc;
    for (int k = 0; k < 32; k++) {
        int ck = ck0 + k;
        gH0c[(size_t)(be*NCHK + ck)*384 + elem] = hrun;
        float hv = gHend[(size_t)(be*NCHK + ck)*384 + elem];
        float Sv = gSsum[(size_t)(be*NCHK + ck)*48 + d];
        hrun = __expf(Sv*A_ds)*hrun + hv;
    }
}

// ---------------- K3: correction + gate + out_proj + residual (fp16 reads) ----------------
__global__ __launch_bounds__(384, 3) void k_output(
    const float* __restrict__ A_log, const float* __restrict__ out_w,
    const float* __restrict__ xext, int useX, int iter)
{
    int ck = blockIdx.x, e = blockIdx.y, b = blockIdx.z;
    int p = 2*iter + e, be = b*2 + e, l0 = ck*CHN, tid = threadIdx.x;

    extern __shared__ float sm[];
    float* s_y    = sm;              // [48][128]
    float* s_Cm   = s_y  + 48*128;   // [8][128]
    float* s_h0   = s_Cm + 8*128;    // [384]
    float* s_A    = s_h0 + 384;      // [384]
    float* s_ow   = s_A  + 384;      // [48][24] transposed
    float* s_fast = s_ow + 1152;     // [48]

    s_h0[tid] = gH0c[(size_t)(be*NCHK + ck)*384 + tid];
    s_A[tid]  = -__expf(A_log[p*384 + tid]);
    for (int i = tid; i < 1152; i += 384) {
        int m = i/48, d = i%48;
        s_ow[d*24 + m] = out_w[p*1152 + i];
    }
    for (int i = tid; i < 8*32; i += 384) {
        int ss = i>>5, tq = (i&31)*4;
        const __half2* src = (const __half2*)&gCmh[(size_t)(be*8 + ss)*LL + l0 + tq];
        float2 a = __half22float2(src[0]), bq = __half22float2(src[1]);
        float4 st = {a.x, a.y, bq.x, bq.y};
        *(float4*)&s_Cm[ss*128 + tq] = st;
    }
    if (tid < 48) {
        float a0 = -__expf(A_log[p*384 + tid*8]);
        float ok = 1.f;
        #pragma unroll
        for (int s = 1; s < 8; s++) {
            float as = -__expf(A_log[p*384 + tid*8 + s]);
            if (fabsf(as - (float)(s+1)*a0) > 1e-4f * fabsf(as)) ok = 0.f;
        }
        s_fast[tid] = ok;
    }
    __syncthreads();

    size_t baseF = (size_t)(be*48)*LL + l0;
    for (int itx = tid; itx < 48*32; itx += 384) {
        int d = itx>>5, tq = (itx&31)*4;
        size_t g = baseF + (size_t)d*LL + tq;
        float4 sd4 = *(const float4*)&gSdt[g];
        const __half2* pY = (const __half2*)&gY0h[g];
        const __half2* pZ = (const __half2*)&gZsh[g];
        float2 ya = __half22float2(pY[0]), yb = __half22float2(pY[1]);
        float2 za = __half22float2(pZ[0]), zb = __half22float2(pZ[1]);
        float acc[4] = {ya.x, ya.y, yb.x, yb.y};
        if (s_fast[d] != 0.f) {
            float A0d = s_A[d*8];
            float r0 = __expf(sd4.x*A0d), r1 = __expf(sd4.y*A0d);
            float r2 = __expf(sd4.z*A0d), r3 = __expf(sd4.w*A0d);
            float p0 = r0, p1 = r1, p2 = r2, p3 = r3;
            #pragma unroll
            for (int s = 0; s < 8; s++) {
                float4 cm = *(const float4*)&s_Cm[s*128 + tq];
                float hh = s_h0[d*8 + s];
                acc[0] += cm.x*p0*hh; acc[1] += cm.y*p1*hh;
                acc[2] += cm.z*p2*hh; acc[3] += cm.w*p3*hh;
                p0 *= r0; p1 *= r1; p2 *= r2; p3 *= r3;
            }
        } else {
            float sdv[4] = {sd4.x, sd4.y, sd4.z, sd4.w};
            #pragma unroll
            for (int s = 0; s < 8; s++) {
                float4 cm = *(const float4*)&s_Cm[s*128 + tq];
                float hh = s_h0[d*8 + s];
                float As = s_A[d*8 + s];
                acc[0] += cm.x*__expf(sdv[0]*As)*hh;
                acc[1] += cm.y*__expf(sdv[1]*As)*hh;
                acc[2] += cm.z*__expf(sdv[2]*As)*hh;
                acc[3] += cm.w*__expf(sdv[3]*As)*hh;
            }
        }
        float4 yq = {acc[0]*za.x, acc[1]*za.y, acc[2]*zb.x, acc[3]*zb.y};
        *(float4*)&s_y[d*128 + tq] = yq;
    }
    __syncthreads();

    const float* resb = (useX ? xext : (const float*)gXf);
    if (tid < 192) {
        int mt = tid/32, tq = (tid%32)*4;
        float acc[4][4] = {};
        #pragma unroll
        for (int dd = 0; dd < 48; dd++) {
            float4 wq = *(const float4*)&s_ow[dd*24 + mt*4];
            float4 yv = *(const float4*)&s_y[dd*128 + tq];
            acc[0][0]+=wq.x*yv.x; acc[0][1]+=wq.x*yv.y; acc[0][2]+=wq.x*yv.z; acc[0][3]+=wq.x*yv.w;
            acc[1][0]+=wq.y*yv.x; acc[1][1]+=wq.y*yv.y; acc[1][2]+=wq.y*yv.z; acc[1][3]+=wq.y*yv.w;
            acc[2][0]+=wq.z*yv.x; acc[2][1]+=wq.z*yv.y; acc[2][2]+=wq.z*yv.z; acc[2][3]+=wq.z*yv.w;
            acc[3][0]+=wq.w*yv.x; acc[3][1]+=wq.w*yv.y; acc[3][2]+=wq.w*yv.z; acc[3][3]+=wq.w*yv.w;
        }
        #pragma unroll
        for (int mm = 0; mm < 4; mm++) {
            int m = mt*4 + mm;
            int c = e*24 + m;
            size_t rowb = (size_t)(b*48 + c)*LL;
            if (e == 0) {
                size_t o = rowb + l0 + tq;
                float4 r = *(const float4*)&resb[o];
                float4 st = {acc[mm][0]+r.x, acc[mm][1]+r.y, acc[mm][2]+r.z, acc[mm][3]+r.w};
                *(float4*)&gYf[o] = st;
            } else {
                size_t o = rowb + (size_t)(LL - 4 - l0 - tq);
                float4 r = *(const float4*)&resb[o];
                float4 st = {acc[mm][3]+r.x, acc[mm][2]+r.y, acc[mm][1]+r.z, acc[mm][0]+r.w};
                *(float4*)&gYf[o] = st;
            }
        }
    }
}

#define SM_F ((2*48*PAD + 2304 + 192 + 48 + 960 + 96 + 48 + 48 + 48 + 48 + 132 + 132 + 96 + 96) * 4)
#define SM_O ((48*128 + 8*128 + 384 + 384 + 1152 + 48) * 4)

extern "C" void kernel_launch(void* const* d_in, const int* in_sizes, int n_in,
                              void* d_out, int out_size)
{
    const float* x       = (const float*)d_in[0];
    const float* ln_g    = (const float*)d_in[1];
    const float* ln_b    = (const float*)d_in[2];
    const float* in_w    = (const float*)d_in[3];
    const float* conv_w  = (const float*)d_in[4];
    const float* conv_b  = (const float*)d_in[5];
    const float* xproj_w = (const float*)d_in[6];
    const float* dt_w    = (const float*)d_in[7];
    const float* dt_b    = (const float*)d_in[8];
    const float* A_log   = (const float*)d_in[9];
    const float* Dp      = (const float*)d_in[10];
    const float* out_w   = (const float*)d_in[11];
    float* out = (float*)d_out;

    cudaFuncSetAttribute(k_features, cudaFuncAttributeMaxDynamicSharedMemorySize, SM_F);
    cudaFuncSetAttribute(k_output,   cudaFuncAttributeMaxDynamicSharedMemorySize, SM_O);

    dim3 pg(8, 96), pb(32, 32);
    for (int it = 0; it < 3; ++it) {
        int useX = (it == 0) ? 1 : 0;
        k_features<<<dim3(NCHK,2,2), 384, SM_F>>>(ln_g, ln_b, in_w, conv_w, conv_b,
                                                  xproj_w, dt_w, dt_b, A_log, Dp,
                                                  x, useX, it);
        k_combine<<<dim3(4,8), 384>>>(A_log, it);
        k_output<<<dim3(NCHK,2,2), 384, SM_O>>>(A_log, out_w, x, useX, it);
        if (it < 2) k_rot<<<pg, pb>>>();
        else        k_final<<<pg, pb>>>(out, x);
    }
}

// round 17
// speedup vs baseline: 1.7496x; 1.0017x over previous
#include <cuda_runtime.h>
#include <cuda_fp16.h>
#include <math.h>

#define LL   32768
#define CHN  128
#define NCHK 256
#define CHP  131
#define PAD  132

// ---------------- static device scratch ----------------
__device__ float  gXf [2*48*LL];
__device__ float  gYf [2*48*LL];
__device__ __half gY0h[4*48*LL];
__device__ __half gSdh[4*48*LL];
__device__ __half gZsh[4*48*LL];
__device__ __half gCmh[4*8*LL];
__device__ float  gHend[4*NCHK*384];
__device__ float  gSsum[4*NCHK*48];
__device__ float  gH0c [4*NCHK*384];

__device__ __forceinline__ float silu_f(float v) { return __fdividef(v, 1.f + __expf(-v)); }

// ---------------- fused rotation: 8 tiles per block (MLP=8) ----------------
__global__ void k_rot()
{
    __shared__ float tile[8][32][33];
    int bc = blockIdx.y, f0 = blockIdx.x * 8;
    int tx = threadIdx.x, ty = threadIdx.y;
    const float* s = gYf + (size_t)bc * LL;
    float* d = gXf + (size_t)bc * LL;
    #pragma unroll
    for (int k = 0; k < 8; k++)
        tile[k][ty][tx] = s[ty*1024 + (f0+k)*32 + tx];
    __syncthreads();
    #pragma unroll
    for (int k = 0; k < 8; k++)
        d[(f0+k)*1024 + ty*32 + tx] = tile[k][tx][ty];
}

// ---------------- final ----------------
__global__ void k_final(float* extd, const float* __restrict__ xext)
{
    __shared__ float tile[8][32][33];
    int bc = blockIdx.y, f0 = blockIdx.x * 8;
    int tx = threadIdx.x, ty = threadIdx.y;
    const float* s = gYf + (size_t)bc * LL;
    const float* xb = xext + (size_t)bc * LL;
    float* d = extd + (size_t)bc * LL;
    #pragma unroll
    for (int k = 0; k < 8; k++)
        tile[k][ty][tx] = s[ty*1024 + (f0+k)*32 + tx];
    __syncthreads();
    #pragma unroll
    for (int k = 0; k < 8; k++) {
        int o = (f0+k)*1024 + ty*32 + tx;
        d[o] = tile[k][tx][ty] + xb[o];
    }
}

// ---------------- K1: features (LN folded) + register-resident scan ----------------
__global__ __launch_bounds__(384, 2) void k_features(
    const float* __restrict__ ln_g, const float* __restrict__ ln_b,
    const float* __restrict__ in_w, const float* __restrict__ conv_w,
    const float* __restrict__ conv_b, const float* __restrict__ xproj_w,
    const float* __restrict__ dt_w, const float* __restrict__ dt_b,
    const float* __restrict__ A_log, const float* __restrict__ Dpar,
    const float* __restrict__ xext, int useX, int iter)
{
    int ck = blockIdx.x, e = blockIdx.y, b = blockIdx.z;
    int p = 2*iter + e, be = b*2 + e, l0 = ck*CHN, tid = threadIdx.x;

    extern __shared__ float sm[];
    float* s_x    = sm;                 // [48][PAD] RAW x (dead after in_proj)
    float* s_dtin = s_x;                // ALIAS [2][PAD]
    float* s_bt   = s_x + 264;          // ALIAS [2592]
    float* s_xc   = sm + 48*PAD;        // [48][PAD]
    float* s_wi   = s_xc + 48*PAD;      // [24][96]
    float* s_cw   = s_wi + 2304;        // [48][4]
    float* s_cb   = s_cw + 192;
    float* s_xw   = s_cb + 48;          // [48][20]
    float* s_dtw  = s_xw + 960;
    float* s_dtb  = s_dtw + 96;
    float* s_g    = s_dtb + 48;
    float* s_bb   = s_g + 48;
    float* s_Dp   = s_bb + 48;
    float* s_mu   = s_Dp + 48;          // [132]
    float* s_rs   = s_mu + 132;         // [132]
    float* s_S1   = s_rs + 132;         // [96]
    float* s_S2   = s_S1 + 96;          // [96]

    // ---- loads ----
    for (int i = tid; i < 2304; i += 384) {
        int eo = i/24, dd = i%24;
        s_wi[dd*96 + eo] = in_w[p*2304 + i];
    }
    for (int i = tid; i < 192; i += 384) s_cw[i] = conv_w[p*192 + i];
    for (int i = tid; i < 864; i += 384) {
        int e2 = i/48, d = i%48;
        s_xw[d*20 + e2] = xproj_w[p*864 + i];
    }
    for (int i = tid; i < 96; i += 384) s_xw[(i>>1)*20 + 18 + (i&1)] = 0.f;
    for (int i = tid; i < 96; i += 384) s_dtw[i] = dt_w[p*96 + i];
    if (tid < 48) {
        s_cb[tid]  = conv_b[p*48 + tid];  s_dtb[tid] = dt_b[p*48 + tid];
        s_g[tid]   = ln_g[iter*48 + tid]; s_bb[tid]  = ln_b[iter*48 + tid];
        s_Dp[tid]  = Dpar[p*48 + tid];
    }
    const float* xfb = (useX ? xext : (const float*)gXf) + (size_t)b*48*LL;
    for (int i = tid; i < 48*PAD; i += 384) {
        int c = i/PAD, j = i%PAD;
        int l = l0 - 3 + j;
        float v = 0.f;
        if (j < CHP && l >= 0) {
            int t = (e == 0) ? l : (LL - 1 - l);
            v = xfb[(size_t)c*LL + t];
        }
        s_x[i] = v;
    }
    __syncthreads();

    // ---- phase A: LN stats + folded-weight sums ----
    int c0 = e*24;
    if (tid < CHP) {
        int j = tid;
        float su = 0.f, sq = 0.f;
        #pragma unroll
        for (int c = 0; c < 48; c++) { float xv = s_x[c*PAD + j]; su += xv; sq += xv*xv; }
        float mu = su*(1.f/48.f);
        float var = sq*(1.f/48.f) - mu*mu;
        s_mu[j] = mu;
        s_rs[j] = rsqrtf(var + 1e-5f);
    }
    if (tid >= 288) {
        int eo = tid - 288;
        const float* wrow = in_w + p*2304 + eo*24;
        float s1 = 0.f, s2 = 0.f;
        #pragma unroll
        for (int dd = 0; dd < 24; dd++) {
            float w = wrow[dd];
            s1 += w*s_g[c0 + dd];
            s2 += w*s_bb[c0 + dd];
        }
        s_S1[eo] = s1; s_S2[eo] = s2;
    }
    for (int i = tid; i < 2304; i += 384) {
        int dd = i/96;
        s_wi[i] *= s_g[c0 + dd];
    }
    __syncthreads();

    // ---- in_proj on RAW x, LN folded, 8e x 4j tiles ----
    for (int itx = tid; itx < 12*33; itx += 384) {
        int eg = itx/33, jg = itx%33;
        int e8 = eg*8, j4 = jg*4;
        float acc[8][4] = {};
        #pragma unroll
        for (int dd = 0; dd < 24; dd++) {
            float4 xv = *(const float4*)&s_x[(c0+dd)*PAD + j4];
            float4 w0 = *(const float4*)&s_wi[dd*96 + e8];
            float4 w1 = *(const float4*)&s_wi[dd*96 + e8 + 4];
            float wv[8] = {w0.x,w0.y,w0.z,w0.w,w1.x,w1.y,w1.z,w1.w};
            #pragma unroll
            for (int ee = 0; ee < 8; ee++) {
                acc[ee][0] += wv[ee]*xv.x; acc[ee][1] += wv[ee]*xv.y;
                acc[ee][2] += wv[ee]*xv.z; acc[ee][3] += wv[ee]*xv.w;
            }
        }
        int gl = l0 - 3 + j4;
        float muv[4] = { s_mu[j4], s_mu[j4+1], s_mu[j4+2], s_mu[j4+3] };
        float rsv[4] = { s_rs[j4], s_rs[j4+1], s_rs[j4+2], s_rs[j4+3] };
        #pragma unroll
        for (int ee = 0; ee < 8; ee++) {
            int eo = e8 + ee;
            float S1v = s_S1[eo], S2v = s_S2[eo];
            #pragma unroll
            for (int jj = 0; jj < 4; jj++) {
                int j = j4 + jj;
                if (j >= CHP) continue;
                float v = rsv[jj]*(acc[ee][jj] - muv[jj]*S1v) + S2v;
                if (gl + jj < 0) v = 0.f;
                if (eo < 48) s_xc[eo*PAD + j] = v;
                else if (j >= 3)
                    gZsh[((size_t)(be*48) + (eo-48))*LL + (size_t)(l0 + j - 3)] =
                        __float2half_rn(silu_f(v));
            }
        }
    }
    __syncthreads();

    // ---- causal conv(4) + silu, vectorized, in place via register staging ----
    {
        float4 ov[4];
        #pragma unroll
        for (int k = 0; k < 4; k++) {
            int q = tid + k*384;
            int d = q>>5, tq = (q&31)*4;
            float4 a  = *(const float4*)&s_xc[d*PAD + tq];
            float4 bq = *(const float4*)&s_xc[d*PAD + tq + 4];
            float w0 = s_cw[d*4+0], w1 = s_cw[d*4+1], w2 = s_cw[d*4+2], w3 = s_cw[d*4+3];
            float cb = s_cb[d];
            float o0 = cb + w0*a.x + w1*a.y + w2*a.z + w3*a.w;
            float o1 = cb + w0*a.y + w1*a.z + w2*a.w + w3*bq.x;
            float o2 = cb + w0*a.z + w1*a.w + w2*bq.x + w3*bq.y;
            float o3 = cb + w0*a.w + w1*bq.x + w2*bq.y + w3*bq.z;
            ov[k].x = silu_f(o0); ov[k].y = silu_f(o1);
            ov[k].z = silu_f(o2); ov[k].w = silu_f(o3);
        }
        __syncthreads();
        #pragma unroll
        for (int k = 0; k < 4; k++) {
            int q = tid + k*384;
            int d = q>>5, tq = (q&31)*4;
            *(float4*)&s_xc[d*PAD + tq] = ov[k];
        }
    }
    __syncthreads();

    // ---- x_proj: 2e2 x 4tok tiles, 288 threads, float2 weights ----
    if (tid < 288) {
        int et = tid/32, tq4 = (tid%32)*4;
        float acc[2][4] = {};
        #pragma unroll
        for (int d = 0; d < 48; d++) {
            float2 wq = *(const float2*)&s_xw[d*20 + et*2];
            float4 xv = *(const float4*)&s_xc[d*PAD + tq4];
            acc[0][0]+=wq.x*xv.x; acc[0][1]+=wq.x*xv.y; acc[0][2]+=wq.x*xv.z; acc[0][3]+=wq.x*xv.w;
            acc[1][0]+=wq.y*xv.x; acc[1][1]+=wq.y*xv.y; acc[1][2]+=wq.y*xv.z; acc[1][3]+=wq.y*xv.w;
        }
        #pragma unroll
        for (int ee = 0; ee < 2; ee++) {
            int e2 = et*2 + ee;
            if (e2 < 2) {
                float4 st = {acc[ee][0], acc[ee][1], acc[ee][2], acc[ee][3]};
                *(float4*)&s_dtin[e2*PAD + tq4] = st;
            } else {
                int c = e2 - 2;
                int swz = ((tq4 >> 4) & 7) * 4;
                #pragma unroll
                for (int k = 0; k < 4; k++)
                    s_bt[(tq4+k)*20 + swz + c] = acc[ee][k];
            }
        }
    }
    __syncthreads();

    // gCm write (fp16, reads s_bt only)
    for (int itx = tid; itx < 8*CHN; itx += 384) {
        int ss = itx>>7, t = itx&127;
        gCmh[(size_t)(be*8 + ss)*LL + l0 + t] =
            __float2half_rn(s_bt[t*20 + ((t>>4)&7)*4 + 8 + ss]);
    }

    // ---- register-resident hierarchical scan: thread = (d, sub of 16 tokens) ----
    {
        int d = tid >> 3, sub = tid & 7;
        int t0 = sub * 16;
        const float* Aptr = A_log + p*384 + d*8;
        float A0 = -__expf(Aptr[0]);
        bool fast = true;
        #pragma unroll
        for (int s = 1; s < 8; s++) {
            float as = -__expf(Aptr[s]);
            if (fabsf(as - (float)(s+1)*A0) > 1e-4f*fabsf(as)) fast = false;
        }

        // dt = softplus(dt_in @ dtw^T + dtb)
        float dtv[16];
        {
            float w0 = s_dtw[d*2], w1 = s_dtw[d*2+1], bs0 = s_dtb[d];
            #pragma unroll
            for (int k = 0; k < 4; k++) {
                float4 a0v = *(const float4*)&s_dtin[t0 + k*4];
                float4 a1v = *(const float4*)&s_dtin[PAD + t0 + k*4];
                float vv0 = bs0 + w0*a0v.x + w1*a1v.x;
                float vv1 = bs0 + w0*a0v.y + w1*a1v.y;
                float vv2 = bs0 + w0*a0v.z + w1*a1v.z;
                float vv3 = bs0 + w0*a0v.w + w1*a1v.w;
                dtv[k*4+0] = (vv0 > 20.f) ? vv0 : __logf(1.f + __expf(vv0));
                dtv[k*4+1] = (vv1 > 20.f) ? vv1 : __logf(1.f + __expf(vv1));
                dtv[k*4+2] = (vv2 > 20.f) ? vv2 : __logf(1.f + __expf(vv2));
                dtv[k*4+3] = (vv3 > 20.f) ? vv3 : __logf(1.f + __expf(vv3));
            }
        }

        float h[8] = {0,0,0,0,0,0,0,0};
        float y0l[16];
        float run = 0.f;
        if (fast) {
            #pragma unroll
            for (int k = 0; k < 4; k++) {
                float4 xcq = *(const float4*)&s_xc[d*PAD + t0 + k*4];
                float xcl[4] = {xcq.x, xcq.y, xcq.z, xcq.w};
                #pragma unroll
                for (int j = 0; j < 4; j++) {
                    int tt = k*4 + j, t = t0 + tt;
                    float dv = dtv[tt];
                    float dx = dv * xcl[j];
                    const float* rb = &s_bt[t*20 + sub*4];
                    float4 b0 = *(const float4*)rb;
                    float4 b1 = *(const float4*)(rb+4);
                    float4 cv0 = *(const float4*)(rb+8);
                    float4 cv1 = *(const float4*)(rb+12);
                    float q = __expf(dv * A0), pc = q;
                    float y0 = 0.f;
                    h[0] = pc*h[0] + dx*b0.x; y0 += h[0]*cv0.x; pc *= q;
                    h[1] = pc*h[1] + dx*b0.y; y0 += h[1]*cv0.y; pc *= q;
                    h[2] = pc*h[2] + dx*b0.z; y0 += h[2]*cv0.z; pc *= q;
                    h[3] = pc*h[3] + dx*b0.w; y0 += h[3]*cv0.w; pc *= q;
                    h[4] = pc*h[4] + dx*b1.x; y0 += h[4]*cv1.x; pc *= q;
                    h[5] = pc*h[5] + dx*b1.y; y0 += h[5]*cv1.y; pc *= q;
                    h[6] = pc*h[6] + dx*b1.z; y0 += h[6]*cv1.z; pc *= q;
                    h[7] = pc*h[7] + dx*b1.w; y0 += h[7]*cv1.w;
                    y0l[tt] = y0;
                    run += dv;
                    dtv[tt] = run;
                }
            }
        } else {
            #pragma unroll
            for (int k = 0; k < 4; k++) {
                float4 xcq = *(const float4*)&s_xc[d*PAD + t0 + k*4];
                float xcl[4] = {xcq.x, xcq.y, xcq.z, xcq.w};
                #pragma unroll
                for (int j = 0; j < 4; j++) {
                    int tt = k*4 + j, t = t0 + tt;
                    float dv = dtv[tt];
                    float dx = dv * xcl[j];
                    const float* rb = &s_bt[t*20 + sub*4];
                    float4 b0 = *(const float4*)rb;
                    float4 b1 = *(const float4*)(rb+4);
                    float4 cv0 = *(const float4*)(rb+8);
                    float4 cv1 = *(const float4*)(rb+12);
                    float Bv[8] = {b0.x,b0.y,b0.z,b0.w,b1.x,b1.y,b1.z,b1.w};
                    float Cv[8] = {cv0.x,cv0.y,cv0.z,cv0.w,cv1.x,cv1.y,cv1.z,cv1.w};
                    float y0 = 0.f;
                    #pragma unroll
                    for (int s = 0; s < 8; s++) {
                        float as = -__expf(Aptr[s]);
                        h[s] = __expf(dv*as)*h[s] + dx*Bv[s];
                        y0 += h[s]*Cv[s];
                    }
                    y0l[tt] = y0;
                    run += dv;
                    dtv[tt] = run;
                }
            }
        }

        // Kogge-Stone inclusive scan over 8 subs
        float S = run;
        #pragma unroll
        for (int st = 1; st < 8; st <<= 1) {
            float Sp = __shfl_up_sync(0xFFFFFFFFu, S, st, 8);
            float hp[8];
            #pragma unroll
            for (int s = 0; s < 8; s++) hp[s] = __shfl_up_sync(0xFFFFFFFFu, h[s], st, 8);
            if (sub >= st) {
                if (fast) {
                    float q = __expf(S * A0), pc = q;
                    #pragma unroll
                    for (int s = 0; s < 8; s++) { h[s] = pc*hp[s] + h[s]; pc *= q; }
                } else {
                    #pragma unroll
                    for (int s = 0; s < 8; s++) {
                        float as = -__expf(Aptr[s]);
                        h[s] = __expf(S*as)*hp[s] + h[s];
                    }
                }
                S += Sp;
            }
        }
        float Hex[8], Sex;
        #pragma unroll
        for (int s = 0; s < 8; s++) Hex[s] = __shfl_up_sync(0xFFFFFFFFu, h[s], 1, 8);
        Sex = __shfl_up_sync(0xFFFFFFFFu, S, 1, 8);
        if (sub == 0) {
            Sex = 0.f;
            #pragma unroll
            for (int s = 0; s < 8; s++) Hex[s] = 0.f;
        }
        if (sub == 7) {
            #pragma unroll
            for (int s = 0; s < 8; s++)
                gHend[(size_t)(be*NCHK + ck)*384 + d*8 + s] = h[s];
            gSsum[(size_t)(be*NCHK + ck)*48 + d] = S;
        }

        // pass 2: carry correction + fp16 gY0/gSdt stores
        float Dpd = s_Dp[d];
        size_t gb = (size_t)(be*48 + d)*LL + l0 + t0;
        #pragma unroll
        for (int k = 0; k < 4; k++) {
            float4 xcq = *(const float4*)&s_xc[d*PAD + t0 + k*4];
            float xcl[4] = {xcq.x, xcq.y, xcq.z, xcq.w};
            float yo[4], so[4];
            #pragma unroll
            for (int j = 0; j < 4; j++) {
                int tt = k*4 + j, t = t0 + tt;
                float Sloc = dtv[tt];
                float y = y0l[tt];
                const float* rb = &s_bt[t*20 + sub*4 + 8];
                float4 cv0 = *(const float4*)rb;
                float4 cv1 = *(const float4*)(rb+4);
                if (fast) {
                    float r = __expf(Sloc * A0), pc = r;
                    y += cv0.x*pc*Hex[0]; pc *= r;
                    y += cv0.y*pc*Hex[1]; pc *= r;
                    y += cv0.z*pc*Hex[2]; pc *= r;
                    y += cv0.w*pc*Hex[3]; pc *= r;
                    y += cv1.x*pc*Hex[4]; pc *= r;
                    y += cv1.y*pc*Hex[5]; pc *= r;
                    y += cv1.z*pc*Hex[6]; pc *= r;
                    y += cv1.w*pc*Hex[7];
                } else {
                    float Cv[8] = {cv0.x,cv0.y,cv0.z,cv0.w,cv1.x,cv1.y,cv1.z,cv1.w};
                    #pragma unroll
                    for (int s = 0; s < 8; s++) {
                        float as = -__expf(Aptr[s]);
                        y += Cv[s]*__expf(Sloc*as)*Hex[s];
                    }
                }
                yo[j] = y + xcl[j]*Dpd;
                so[j] = Sloc + Sex;
            }
            __half2* pY = (__half2*)&gY0h[gb + k*4];
            pY[0] = __floats2half2_rn(yo[0], yo[1]);
            pY[1] = __floats2half2_rn(yo[2], yo[3]);
            __half2* pS = (__half2*)&gSdh[gb + k*4];
            pS[0] = __floats2half2_rn(so[0], so[1]);
            pS[1] = __floats2half2_rn(so[2], so[3]);
        }
    }
}

// ---------------- K2: parallel carry combine ----------------
__global__ __launch_bounds__(384) void k_combine(const float* __restrict__ A_log, int iter)
{
    int be = blockIdx.x, e = be & 1, p = 2*iter + e;
    int grp = blockIdx.y;
    int tid = threadIdx.x;
    int elem = grp*48 + (tid >> 3);
    int sub = tid & 7;
    int d = elem >> 3;
    float A_ds = -expf(A_log[p*384 + elem]);
    int ck0 = sub * 32;

    float hrun = 0.f, Ssum = 0.f;
    for (int k = 0; k < 32; k++) {
        int ck = ck0 + k;
        float hv = gHend[(size_t)(be*NCHK + ck)*384 + elem];
        float Sv = gSsum[(size_t)(be*NCHK + ck)*48 + d];
        hrun = __expf(Sv*A_ds)*hrun + hv;
        Ssum += Sv;
    }
    float H = hrun, S = Ssum;
    #pragma unroll
    for (int st = 1; st < 8; st <<= 1) {
        float Hp = __shfl_up_sync(0xFFFFFFFFu, H, st, 8);
        float Sp = __shfl_up_sync(0xFFFFFFFFu, S, st, 8);
        if (sub >= st) { H = __expf(S*A_ds)*Hp + H; S += Sp; }
    }
    float Hexc = __shfl_up_sync(0xFFFFFFFFu, H, 1, 8);
    if (sub == 0) Hexc = 0.f;
    hrun = Hexc;
    for (int k = 0; k < 32; k++) {
        int ck = ck0 + k;
        gH0c[(size_t)(be*NCHK + ck)*384 + elem] = hrun;
        float hv = gHend[(size_t)(be*NCHK + ck)*384 + elem];
        float Sv = gSsum[(size_t)(be*NCHK + ck)*48 + d];
        hrun = __expf(Sv*A_ds)*hrun + hv;
    }
}

// ---------------- K3: correction + gate + out_proj + residual (fp16 reads) ----------------
__global__ __launch_bounds__(384, 3) void k_output(
    const float* __restrict__ A_log, const float* __restrict__ out_w,
    const float* __restrict__ xext, int useX, int iter)
{
    int ck = blockIdx.x, e = blockIdx.y, b = blockIdx.z;
    int p = 2*iter + e, be = b*2 + e, l0 = ck*CHN, tid = threadIdx.x;

    extern __shared__ float sm[];
    float* s_y    = sm;              // [48][128]
    float* s_Cm   = s_y  + 48*128;   // [8][128]
    float* s_h0   = s_Cm + 8*128;    // [384]
    float* s_A    = s_h0 + 384;      // [384]
    float* s_ow   = s_A  + 384;      // [48][24] transposed
    float* s_fast = s_ow + 1152;     // [48]

    s_h0[tid] = gH0c[(size_t)(be*NCHK + ck)*384 + tid];
    s_A[tid]  = -__expf(A_log[p*384 + tid]);
    for (int i = tid; i < 1152; i += 384) {
        int m = i/48, d = i%48;
        s_ow[d*24 + m] = out_w[p*1152 + i];
    }
    for (int i = tid; i < 8*32; i += 384) {
        int ss = i>>5, tq = (i&31)*4;
        const __half2* src = (const __half2*)&gCmh[(size_t)(be*8 + ss)*LL + l0 + tq];
        float2 a = __half22float2(src[0]), bq = __half22float2(src[1]);
        float4 st = {a.x, a.y, bq.x, bq.y};
        *(float4*)&s_Cm[ss*128 + tq] = st;
    }
    if (tid < 48) {
        float a0 = -__expf(A_log[p*384 + tid*8]);
        float ok = 1.f;
        #pragma unroll
        for (int s = 1; s < 8; s++) {
            float as = -__expf(A_log[p*384 + tid*8 + s]);
            if (fabsf(as - (float)(s+1)*a0) > 1e-4f * fabsf(as)) ok = 0.f;
        }
        s_fast[tid] = ok;
    }
    __syncthreads();

    size_t baseF = (size_t)(be*48)*LL + l0;
    for (int itx = tid; itx < 48*32; itx += 384) {
        int d = itx>>5, tq = (itx&31)*4;
        size_t g = baseF + (size_t)d*LL + tq;
        const __half2* pS = (const __half2*)&gSdh[g];
        const __half2* pY = (const __half2*)&gY0h[g];
        const __half2* pZ = (const __half2*)&gZsh[g];
        float2 sa = __half22float2(pS[0]), sb = __half22float2(pS[1]);
        float2 ya = __half22float2(pY[0]), yb = __half22float2(pY[1]);
        float2 za = __half22float2(pZ[0]), zb = __half22float2(pZ[1]);
        float4 sd4 = {sa.x, sa.y, sb.x, sb.y};
        float acc[4] = {ya.x, ya.y, yb.x, yb.y};
        if (s_fast[d] != 0.f) {
            float A0d = s_A[d*8];
            float r0 = __expf(sd4.x*A0d), r1 = __expf(sd4.y*A0d);
            float r2 = __expf(sd4.z*A0d), r3 = __expf(sd4.w*A0d);
            float p0 = r0, p1 = r1, p2 = r2, p3 = r3;
            #pragma unroll
            for (int s = 0; s < 8; s++) {
                float4 cm = *(const float4*)&s_Cm[s*128 + tq];
                float hh = s_h0[d*8 + s];
                acc[0] += cm.x*p0*hh; acc[1] += cm.y*p1*hh;
                acc[2] += cm.z*p2*hh; acc[3] += cm.w*p3*hh;
                p0 *= r0; p1 *= r1; p2 *= r2; p3 *= r3;
            }
        } else {
            float sdv[4] = {sd4.x, sd4.y, sd4.z, sd4.w};
            #pragma unroll
            for (int s = 0; s < 8; s++) {
                float4 cm = *(const float4*)&s_Cm[s*128 + tq];
                float hh = s_h0[d*8 + s];
                float As = s_A[d*8 + s];
                acc[0] += cm.x*__expf(sdv[0]*As)*hh;
                acc[1] += cm.y*__expf(sdv[1]*As)*hh;
                acc[2] += cm.z*__expf(sdv[2]*As)*hh;
                acc[3] += cm.w*__expf(sdv[3]*As)*hh;
            }
        }
        float4 yq = {acc[0]*za.x, acc[1]*za.y, acc[2]*zb.x, acc[3]*zb.y};
        *(float4*)&s_y[d*128 + tq] = yq;
    }
    __syncthreads();

    const float* resb = (useX ? xext : (const float*)gXf);
    if (tid < 192) {
        int mt = tid/32, tq = (tid%32)*4;
        float acc[4][4] = {};
        #pragma unroll
        for (int dd = 0; dd < 48; dd++) {
            float4 wq = *(const float4*)&s_ow[dd*24 + mt*4];
            float4 yv = *(const float4*)&s_y[dd*128 + tq];
            acc[0][0]+=wq.x*yv.x; acc[0][1]+=wq.x*yv.y; acc[0][2]+=wq.x*yv.z; acc[0][3]+=wq.x*yv.w;
            acc[1][0]+=wq.y*yv.x; acc[1][1]+=wq.y*yv.y; acc[1][2]+=wq.y*yv.z; acc[1][3]+=wq.y*yv.w;
            acc[2][0]+=wq.z*yv.x; acc[2][1]+=wq.z*yv.y; acc[2][2]+=wq.z*yv.z; acc[2][3]+=wq.z*yv.w;
            acc[3][0]+=wq.w*yv.x; acc[3][1]+=wq.w*yv.y; acc[3][2]+=wq.w*yv.z; acc[3][3]+=wq.w*yv.w;
        }
        #pragma unroll
        for (int mm = 0; mm < 4; mm++) {
            int m = mt*4 + mm;
            int c = e*24 + m;
            size_t rowb = (size_t)(b*48 + c)*LL;
            if (e == 0) {
                size_t o = rowb + l0 + tq;
                float4 r = *(const float4*)&resb[o];
                float4 st = {acc[mm][0]+r.x, acc[mm][1]+r.y, acc[mm][2]+r.z, acc[mm][3]+r.w};
                *(float4*)&gYf[o] = st;
            } else {
                size_t o = rowb + (size_t)(LL - 4 - l0 - tq);
                float4 r = *(const float4*)&resb[o];
                float4 st = {acc[mm][3]+r.x, acc[mm][2]+r.y, acc[mm][1]+r.z, acc[mm][0]+r.w};
                *(float4*)&gYf[o] = st;
            }
        }
    }
}

#define SM_F ((2*48*PAD + 2304 + 192 + 48 + 960 + 96 + 48 + 48 + 48 + 48 + 132 + 132 + 96 + 96) * 4)
#define SM_O ((48*128 + 8*128 + 384 + 384 + 1152 + 48) * 4)

extern "C" void kernel_launch(void* const* d_in, const int* in_sizes, int n_in,
                              void* d_out, int out_size)
{
    const float* x       = (const float*)d_in[0];
    const float* ln_g    = (const float*)d_in[1];
    const float* ln_b    = (const float*)d_in[2];
    const float* in_w    = (const float*)d_in[3];
    const float* conv_w  = (const float*)d_in[4];
    const float* conv_b  = (const float*)d_in[5];
    const float* xproj_w = (const float*)d_in[6];
    const float* dt_w    = (const float*)d_in[7];
    const float* dt_b    = (const float*)d_in[8];
    const float* A_log   = (const float*)d_in[9];
    const float* Dp      = (const float*)d_in[10];
    const float* out_w   = (const float*)d_in[11];
    float* out = (float*)d_out;

    cudaFuncSetAttribute(k_features, cudaFuncAttributeMaxDynamicSharedMemorySize, SM_F);
    cudaFuncSetAttribute(k_output,   cudaFuncAttributeMaxDynamicSharedMemorySize, SM_O);

    dim3 pg(4, 96), pb(32, 32);
    for (int it = 0; it < 3; ++it) {
        int useX = (it == 0) ? 1 : 0;
        k_features<<<dim3(NCHK,2,2), 384, SM_F>>>(ln_g, ln_b, in_w, conv_w, conv_b,
                                                  xproj_w, dt_w, dt_b, A_log, Dp,
                                                  x, useX, it);
        k_combine<<<dim3(4,8), 384>>>(A_log, it);
        k_output<<<dim3(NCHK,2,2), 384, SM_O>>>(A_log, out_w, x, useX, it);
        if (it < 2) k_rot<<<pg, pb>>>();
        else        k_final<<<pg, pb>>>(out, x);
    }
}